// round 5
// baseline (speedup 1.0000x reference)
#include <cuda_runtime.h>
#include <math.h>

// Problem constants
#define B 4
#define NPTS 8192
#define KNN 20
#define OCH 64
#define EPS 1e-5
#define SLOPE 0.2f
#define INFF __int_as_float(0x7f800000)

// Device scratch (no allocations allowed)
__device__ int    g_idx[B * NPTS * KNN];
__device__ double g_stats[B * 27];
__device__ float  g_mean[B * OCH];
__device__ float  g_rstd[B * OCH];

// ---------------------------------------------------------------------------
// Kernel 0: zero the moment accumulators (must happen every call)
// ---------------------------------------------------------------------------
__global__ void k_init() {
    int t = threadIdx.x;
    if (t < B * 27) g_stats[t] = 0.0;
}

// ---------------------------------------------------------------------------
// Distance: points staged scaled {-2x,-2y,-2z, ||x||^2}; query unscaled.
// d = q.sq + p.sq - 2*dot  computed as fma chain seeded with (qw + p.w).
// Used identically in both phases -> bit-identical distances.
// ---------------------------------------------------------------------------
__device__ __forceinline__ float pdist(float qx, float qy, float qz, float qw,
                                       float4 p) {
    return fmaf(qz, p.z, fmaf(qy, p.y, fmaf(qx, p.x, qw + p.w)));
}

// ---------------------------------------------------------------------------
// Sorted-insertion min/max network: s[] ascending; inserting d keeps the 20
// smallest values. 2 FMNMX per slot, dependency depth 2, and IDEMPOTENT for
// non-improving d -> lanes without a candidate insert +INF harmlessly.
// ---------------------------------------------------------------------------
__device__ __forceinline__ void ins_net(float (&s)[KNN], float de) {
#pragma unroll
    for (int k = KNN - 1; k >= 1; k--)
        s[k] = fminf(s[k], fmaxf(s[k - 1], de));
    s[0] = fminf(s[0], de);
}

// ---------------------------------------------------------------------------
// Kernel 1: two-phase exact KNN + fused moment accumulation.
// Phase A: per-query exact 20th-smallest distance T (values only).
// Phase B: rescan; collect j with d < T (<= 19 of them) plus ties d == T,
// take lowest-j ties to fill exactly 20  == jax top_k boundary semantics.
// All hot-loop branches are gated on __any_sync (warp-coherent execution);
// list updates are branchless (FMNMX network / predicated SEL appends).
// ---------------------------------------------------------------------------
__global__ void k_knn(const float* __restrict__ x) {
    extern __shared__ float4 s_pts[];
    __shared__ double sh[27];

    const int b = blockIdx.y;
    const float* xb = x + b * 3 * NPTS;

    for (int j = threadIdx.x; j < NPTS; j += blockDim.x) {
        float a0 = xb[j];
        float a1 = xb[NPTS + j];
        float a2 = xb[2 * NPTS + j];
        float sq = fmaf(a0, a0, fmaf(a1, a1, a2 * a2));
        s_pts[j] = make_float4(-2.0f * a0, -2.0f * a1, -2.0f * a2, sq);
    }
    __syncthreads();

    const int i = blockIdx.x * blockDim.x + threadIdx.x;
    const float4 ps = s_pts[i];
    const float qx = -0.5f * ps.x, qy = -0.5f * ps.y, qz = -0.5f * ps.z;
    const float qw = ps.w;

    // ---------------- Phase A: top-20 distance values ----------------
    float s[KNN];
#pragma unroll
    for (int k = 0; k < KNN; k++) s[k] = INFF;

#pragma unroll 2
    for (int j0 = 0; j0 < NPTS; j0 += 4) {
        float4 p0 = s_pts[j0 + 0];
        float4 p1 = s_pts[j0 + 1];
        float4 p2 = s_pts[j0 + 2];
        float4 p3 = s_pts[j0 + 3];
        float dA = pdist(qx, qy, qz, qw, p0);
        float dB = pdist(qx, qy, qz, qw, p1);
        float dC = pdist(qx, qy, qz, qw, p2);
        float dD = pdist(qx, qy, qz, qw, p3);
        // stale (pre-group) threshold: superset gating; network is exact anyway
        const float w = s[KNN - 1];
        bool t0 = dA < w, t1 = dB < w, t2 = dC < w, t3 = dD < w;
        if (__any_sync(0xffffffffu, t0)) ins_net(s, t0 ? dA : INFF);
        if (__any_sync(0xffffffffu, t1)) ins_net(s, t1 ? dB : INFF);
        if (__any_sync(0xffffffffu, t2)) ins_net(s, t2 ? dC : INFF);
        if (__any_sync(0xffffffffu, t3)) ins_net(s, t3 ? dD : INFF);
    }
    const float T = s[KNN - 1];   // exact 20th smallest distance

    // ---------------- Phase B: gather indices ----------------
    int m[KNN];
    int tq[8];
    int cnt = 0, ceq = 0;
#pragma unroll
    for (int k = 0; k < KNN; k++) m[k] = 0;
#pragma unroll
    for (int q = 0; q < 8; q++) tq[q] = 0;

#define GATHER(dv, jv) do {                                                   \
        bool _lt = (dv) < T;                                                  \
        if (__any_sync(0xffffffffu, _lt)) {                                   \
            _Pragma("unroll")                                                 \
            for (int _s = 0; _s < KNN; _s++)                                  \
                m[_s] = (_lt && cnt == _s) ? (jv) : m[_s];                    \
            cnt += _lt ? 1 : 0;                                               \
        }                                                                     \
        bool _eq = ((dv) == T) && (ceq < 8);                                  \
        if (__any_sync(0xffffffffu, _eq)) {                                   \
            _Pragma("unroll")                                                 \
            for (int _q = 0; _q < 8; _q++)                                    \
                tq[_q] = (_eq && ceq == _q) ? (jv) : tq[_q];                  \
            ceq += _eq ? 1 : 0;                                               \
        }                                                                     \
    } while (0)

#pragma unroll 2
    for (int j0 = 0; j0 < NPTS; j0 += 4) {
        float4 p0 = s_pts[j0 + 0];
        float4 p1 = s_pts[j0 + 1];
        float4 p2 = s_pts[j0 + 2];
        float4 p3 = s_pts[j0 + 3];
        float dA = pdist(qx, qy, qz, qw, p0);
        float dB = pdist(qx, qy, qz, qw, p1);
        float dC = pdist(qx, qy, qz, qw, p2);
        float dD = pdist(qx, qy, qz, qw, p3);
        GATHER(dA, j0 + 0);
        GATHER(dB, j0 + 1);
        GATHER(dC, j0 + 2);
        GATHER(dD, j0 + 3);
    }
#undef GATHER

    // fill remaining slots with lowest-j ties (tq is in ascending j)
#pragma unroll
    for (int q = 0; q < 8; q++) {
        bool en = (q < ceq) && (cnt < KNN);
#pragma unroll
        for (int s2 = 0; s2 < KNN; s2++)
            m[s2] = (en && cnt == s2) ? tq[q] : m[s2];
        cnt += en ? 1 : 0;
    }

    int* op = g_idx + (b * NPTS + i) * KNN;
#pragma unroll
    for (int k = 0; k < KNN; k++) op[k] = m[k];

    // ---------------- fused moment accumulation ----------------
    // deltas: xj - xi = (-0.5*p.x) - qx  (exact power-of-two rescale)
    const float nqx = -qx, nqy = -qy, nqz = -qz;
    float sd0 = 0.f, sd1 = 0.f, sd2 = 0.f;
    float s00 = 0.f, s01 = 0.f, s02 = 0.f, s11 = 0.f, s12 = 0.f, s22 = 0.f;
#pragma unroll
    for (int k = 0; k < KNN; k++) {
        float4 p = s_pts[m[k]];
        float d0 = fmaf(-0.5f, p.x, nqx);
        float d1 = fmaf(-0.5f, p.y, nqy);
        float d2 = fmaf(-0.5f, p.z, nqz);
        sd0 += d0; sd1 += d1; sd2 += d2;
        s00 = fmaf(d0, d0, s00); s01 = fmaf(d0, d1, s01); s02 = fmaf(d0, d2, s02);
        s11 = fmaf(d1, d1, s11); s12 = fmaf(d1, d2, s12); s22 = fmaf(d2, d2, s22);
    }

    float v[27];
    v[0] = KNN * qx; v[1] = KNN * qy; v[2] = KNN * qz;
    v[3] = sd0; v[4] = sd1; v[5] = sd2;
    v[6] = KNN * qx * qx; v[7] = KNN * qx * qy; v[8]  = KNN * qx * qz;
    v[9] = KNN * qy * qy; v[10] = KNN * qy * qz; v[11] = KNN * qz * qz;
    v[12] = qx * sd0; v[13] = qx * sd1; v[14] = qx * sd2;
    v[15] = qy * sd0; v[16] = qy * sd1; v[17] = qy * sd2;
    v[18] = qz * sd0; v[19] = qz * sd1; v[20] = qz * sd2;
    v[21] = s00; v[22] = s01; v[23] = s02; v[24] = s11; v[25] = s12; v[26] = s22;

#pragma unroll
    for (int q = 0; q < 27; q++) {
#pragma unroll
        for (int off = 16; off > 0; off >>= 1)
            v[q] += __shfl_down_sync(0xffffffffu, v[q], off);
    }

    if (threadIdx.x < 27) sh[threadIdx.x] = 0.0;
    __syncthreads();
    if ((threadIdx.x & 31) == 0) {
#pragma unroll
        for (int q = 0; q < 27; q++) atomicAdd(&sh[q], (double)v[q]);
    }
    __syncthreads();
    if (threadIdx.x < 27) atomicAdd(&g_stats[b * 27 + threadIdx.x], sh[threadIdx.x]);
}

// ---------------------------------------------------------------------------
// Kernel 2: per-(b,o) mean / rstd from the quadratic form.  256 threads.
// ---------------------------------------------------------------------------
__global__ void k_norm(const float* __restrict__ W) {
    int t = threadIdx.x;
    int b = t / OCH, o = t % OCH;
    const float* w = W + o * 6;
    double wa0 = w[0], wa1 = w[1], wa2 = w[2];
    double wb0 = w[3], wb1 = w[4], wb2 = w[5];
    const double* G = g_stats + b * 27;
    const double NK = (double)NPTS * (double)KNN;

    double mean = (wa0 * G[0] + wa1 * G[1] + wa2 * G[2] +
                   wb0 * G[3] + wb1 * G[4] + wb2 * G[5]) / NK;

    double xx = wa0 * wa0 * G[6] + 2.0 * wa0 * wa1 * G[7] + 2.0 * wa0 * wa2 * G[8] +
                wa1 * wa1 * G[9] + 2.0 * wa1 * wa2 * G[10] + wa2 * wa2 * G[11];
    double xd = wa0 * (wb0 * G[12] + wb1 * G[13] + wb2 * G[14]) +
                wa1 * (wb0 * G[15] + wb1 * G[16] + wb2 * G[17]) +
                wa2 * (wb0 * G[18] + wb1 * G[19] + wb2 * G[20]);
    double dd = wb0 * wb0 * G[21] + 2.0 * wb0 * wb1 * G[22] + 2.0 * wb0 * wb2 * G[23] +
                wb1 * wb1 * G[24] + 2.0 * wb1 * wb2 * G[25] + wb2 * wb2 * G[26];

    double Ey2 = (xx + 2.0 * xd + dd) / NK;
    double var = Ey2 - mean * mean;
    g_mean[t] = (float)mean;
    g_rstd[t] = (float)(1.0 / sqrt(var + EPS));
}

// ---------------------------------------------------------------------------
// Kernel 3: conv + max over k (monotone: normalize+leaky applied after max).
// ---------------------------------------------------------------------------
__global__ void k_out(const float* __restrict__ x, const float* __restrict__ W,
                      float* __restrict__ out) {
    const int b = blockIdx.y;
    const int n = blockIdx.x * blockDim.x + threadIdx.x;

    __shared__ float sW[OCH * 6];
    __shared__ float sM[OCH];
    __shared__ float sR[OCH];
    for (int t = threadIdx.x; t < OCH * 6; t += blockDim.x) sW[t] = W[t];
    if (threadIdx.x < OCH) {
        sM[threadIdx.x] = g_mean[b * OCH + threadIdx.x];
        sR[threadIdx.x] = g_rstd[b * OCH + threadIdx.x];
    }
    __syncthreads();

    const float* xb = x + b * 3 * NPTS;
    const float xi0 = xb[n], xi1 = xb[NPTS + n], xi2 = xb[2 * NPTS + n];
    const int* ip = g_idx + (b * NPTS + n) * KNN;

    float d0[KNN], d1[KNN], d2[KNN];
#pragma unroll
    for (int k = 0; k < KNN; k++) {
        int j = ip[k];
        d0[k] = xb[j] - xi0;
        d1[k] = xb[NPTS + j] - xi1;
        d2[k] = xb[2 * NPTS + j] - xi2;
    }

    float* ob = out + (size_t)b * OCH * NPTS + n;
    for (int o = 0; o < OCH; o++) {
        float wa0 = sW[o * 6 + 0], wa1 = sW[o * 6 + 1], wa2 = sW[o * 6 + 2];
        float wb0 = sW[o * 6 + 3], wb1 = sW[o * 6 + 4], wb2 = sW[o * 6 + 5];
        float p = wa0 * xi0;
        p = fmaf(wa1, xi1, p);
        p = fmaf(wa2, xi2, p);
        float m = -3.4e38f;
#pragma unroll
        for (int k = 0; k < KNN; k++) {
            float y = fmaf(wb2, d2[k], fmaf(wb1, d1[k], fmaf(wb0, d0[k], p)));
            m = fmaxf(m, y);
        }
        float z = (m - sM[o]) * sR[o];
        ob[(size_t)o * NPTS] = (z >= 0.f) ? z : SLOPE * z;
    }
}

// ---------------------------------------------------------------------------
extern "C" void kernel_launch(void* const* d_in, const int* in_sizes, int n_in,
                              void* d_out, int out_size) {
    const float* x = (const float*)d_in[0];   // [B, C, N]
    const float* W = (const float*)d_in[1];   // [O, 2C]
    float* out = (float*)d_out;               // [B, O, N]

    const int smem_knn = NPTS * sizeof(float4);   // 128 KB
    cudaFuncSetAttribute(k_knn, cudaFuncAttributeMaxDynamicSharedMemorySize, smem_knn);

    dim3 grid(NPTS / 256, B);

    k_init<<<1, 128>>>();
    k_knn<<<grid, 256, smem_knn>>>(x);
    k_norm<<<1, B * OCH>>>(W);
    k_out<<<grid, 256>>>(x, W, out);
}

// round 6
// speedup vs baseline: 2.1753x; 2.1753x over previous
#include <cuda_runtime.h>
#include <math.h>
#include <stdint.h>

// Problem constants
#define B 4
#define NPTS 8192
#define KNN 20
#define OCH 64
#define EPS 1e-5
#define SLOPE 0.2f
#define INFF __int_as_float(0x7f800000)

// dynamic smem layout: [0,128K) staged points, [128K,192K) per-lane queues
#define PTS_BYTES (NPTS * 16)
#define BUF_BYTES (8 * 32 * 32 * 8)     // 8 warps x 32 entries x 32 lanes x 8B
#define SMEM_TOTAL (PTS_BYTES + BUF_BYTES)

// Device scratch (no allocations allowed)
__device__ int    g_idx[B * NPTS * KNN];
__device__ double g_stats[B * 27];
__device__ float  g_mean[B * OCH];
__device__ float  g_rstd[B * OCH];

// ---------------------------------------------------------------------------
// Kernel 0: zero the moment accumulators (must happen every call)
// ---------------------------------------------------------------------------
__global__ void k_init() {
    int t = threadIdx.x;
    if (t < B * 27) g_stats[t] = 0.0;
}

// ---------------------------------------------------------------------------
// Branchless stable insertion into sorted-ascending (d, j) list of 20.
// Upper-bound placement (strict <): incoming value lands AFTER existing
// equal-d entries. Since candidates arrive in ascending j, ties are ordered
// by ascending j automatically, and the evicted worst is the largest (d, j)
// lexicographically == jax top_k boundary semantics. Idempotent for vd=+INF.
// All ternaries on scalars -> SELs, no branches.
// ---------------------------------------------------------------------------
__device__ __forceinline__ void insert_dj(float (&sd)[KNN], int (&sj)[KNN],
                                          float vd, int vj) {
    bool c[KNN];
#pragma unroll
    for (int k = 0; k < KNN; k++) c[k] = vd < sd[k];
#pragma unroll
    for (int k = KNN - 1; k >= 1; k--) {
        float td = c[k] ? vd : sd[k];
        int   tj = c[k] ? vj : sj[k];
        sd[k] = c[k - 1] ? sd[k - 1] : td;
        sj[k] = c[k - 1] ? sj[k - 1] : tj;
    }
    sd[0] = c[0] ? vd : sd[0];
    sj[0] = c[0] ? vj : sj[0];
}

// ---------------------------------------------------------------------------
// Kernel 1: single-phase exact KNN + fused moment accumulation.
// Hot loop is branch-free: candidates go to a lane-private smem queue via a
// PTX-predicated store (no BSSY). One uniform drain-check branch per 16 pts.
// Drain merges queued candidates into the register-resident sorted list.
// ---------------------------------------------------------------------------
__global__ void k_knn(const float* __restrict__ x) {
    extern __shared__ char sm[];
    float4* s_pts = (float4*)sm;
    __shared__ double sh[27];

    const int b = blockIdx.y;
    const float* xb = x + b * 3 * NPTS;

    // stage points scaled {-2x,-2y,-2z, ||x||^2}
    for (int j = threadIdx.x; j < NPTS; j += blockDim.x) {
        float a0 = xb[j];
        float a1 = xb[NPTS + j];
        float a2 = xb[2 * NPTS + j];
        float sq = fmaf(a0, a0, fmaf(a1, a1, a2 * a2));
        s_pts[j] = make_float4(-2.0f * a0, -2.0f * a1, -2.0f * a2, sq);
    }
    __syncthreads();

    const int tid = threadIdx.x;
    const int i = blockIdx.x * blockDim.x + tid;
    const float4 ps = s_pts[i];
    const float qx = -0.5f * ps.x, qy = -0.5f * ps.y, qz = -0.5f * ps.z;
    const float qw = ps.w;

    // lane-private queue: entry e at byte offset e*256 from bufA
    uint32_t sbase;
    asm("{ .reg .u64 t; cvta.to.shared.u64 t, %1; cvt.u32.u64 %0, t; }"
        : "=r"(sbase) : "l"(sm));
    const uint32_t bufA = sbase + (uint32_t)PTS_BYTES +
                          (uint32_t)(tid >> 5) * 8192u + (uint32_t)(tid & 31) * 8u;
    const float2* bufP = (const float2*)(sm + PTS_BYTES +
                          (tid >> 5) * 8192 + (tid & 31) * 8);

    float sd[KNN];
    int   sj[KNN];
#pragma unroll
    for (int k = 0; k < KNN; k++) { sd[k] = INFF; sj[k] = 0; }
    float worst = INFF;   // stays INF until list holds 20 real entries
    int   cnt = 0;

#define DRAIN() do {                                                   \
        for (int e = 0; __any_sync(0xffffffffu, e < cnt); e++) {       \
            float2 v = bufP[e * 32];                                   \
            float vd = (e < cnt) ? v.x : INFF;                         \
            insert_dj(sd, sj, vd, __float_as_int(v.y));                \
        }                                                              \
        worst = sd[KNN - 1];                                           \
        cnt = 0;                                                       \
    } while (0)

    for (int j0 = 0; j0 < NPTS; j0 += 16) {
#pragma unroll
        for (int u = 0; u < 16; u++) {
            const int j = j0 + u;
            float4 p = s_pts[j];
            float d = fmaf(qz, p.z, fmaf(qy, p.y, fmaf(qx, p.x, qw + p.w)));
            bool t = d < worst;                       // strict <: exact (see proof)
            uint32_t a = bufA + (uint32_t)cnt * 256u;
            asm volatile(
                "{ .reg .pred p; setp.ne.u32 p, %0, 0;"
                "  @p st.shared.v2.b32 [%1], {%2, %3}; }"
                :: "r"((uint32_t)t), "r"(a), "r"(__float_as_int(d)), "r"(j)
                : "memory");
            cnt += t;
        }
        // cap proof: post-check cnt <= 15, +16 -> <= 31 < 32 slots
        if (__any_sync(0xffffffffu, cnt >= 16)) DRAIN();
    }
    DRAIN();   // leftovers
#undef DRAIN

    int* op = g_idx + (b * NPTS + i) * KNN;
#pragma unroll
    for (int k = 0; k < KNN; k++) op[k] = sj[k];

    // ---------------- fused moment accumulation ----------------
    // deltas: xj - xi = (-0.5*p.x) - qx  (exact power-of-two rescale)
    const float nqx = -qx, nqy = -qy, nqz = -qz;
    float sd0 = 0.f, sd1 = 0.f, sd2 = 0.f;
    float s00 = 0.f, s01 = 0.f, s02 = 0.f, s11 = 0.f, s12 = 0.f, s22 = 0.f;
#pragma unroll
    for (int k = 0; k < KNN; k++) {
        float4 p = s_pts[sj[k]];
        float d0 = fmaf(-0.5f, p.x, nqx);
        float d1 = fmaf(-0.5f, p.y, nqy);
        float d2 = fmaf(-0.5f, p.z, nqz);
        sd0 += d0; sd1 += d1; sd2 += d2;
        s00 = fmaf(d0, d0, s00); s01 = fmaf(d0, d1, s01); s02 = fmaf(d0, d2, s02);
        s11 = fmaf(d1, d1, s11); s12 = fmaf(d1, d2, s12); s22 = fmaf(d2, d2, s22);
    }

    float v[27];
    v[0] = KNN * qx; v[1] = KNN * qy; v[2] = KNN * qz;
    v[3] = sd0; v[4] = sd1; v[5] = sd2;
    v[6] = KNN * qx * qx; v[7] = KNN * qx * qy; v[8]  = KNN * qx * qz;
    v[9] = KNN * qy * qy; v[10] = KNN * qy * qz; v[11] = KNN * qz * qz;
    v[12] = qx * sd0; v[13] = qx * sd1; v[14] = qx * sd2;
    v[15] = qy * sd0; v[16] = qy * sd1; v[17] = qy * sd2;
    v[18] = qz * sd0; v[19] = qz * sd1; v[20] = qz * sd2;
    v[21] = s00; v[22] = s01; v[23] = s02; v[24] = s11; v[25] = s12; v[26] = s22;

#pragma unroll
    for (int q = 0; q < 27; q++) {
#pragma unroll
        for (int off = 16; off > 0; off >>= 1)
            v[q] += __shfl_down_sync(0xffffffffu, v[q], off);
    }

    if (threadIdx.x < 27) sh[threadIdx.x] = 0.0;
    __syncthreads();
    if ((threadIdx.x & 31) == 0) {
#pragma unroll
        for (int q = 0; q < 27; q++) atomicAdd(&sh[q], (double)v[q]);
    }
    __syncthreads();
    if (threadIdx.x < 27) atomicAdd(&g_stats[b * 27 + threadIdx.x], sh[threadIdx.x]);
}

// ---------------------------------------------------------------------------
// Kernel 2: per-(b,o) mean / rstd from the quadratic form.  256 threads.
// ---------------------------------------------------------------------------
__global__ void k_norm(const float* __restrict__ W) {
    int t = threadIdx.x;
    int b = t / OCH, o = t % OCH;
    const float* w = W + o * 6;
    double wa0 = w[0], wa1 = w[1], wa2 = w[2];
    double wb0 = w[3], wb1 = w[4], wb2 = w[5];
    const double* G = g_stats + b * 27;
    const double NK = (double)NPTS * (double)KNN;

    double mean = (wa0 * G[0] + wa1 * G[1] + wa2 * G[2] +
                   wb0 * G[3] + wb1 * G[4] + wb2 * G[5]) / NK;

    double xx = wa0 * wa0 * G[6] + 2.0 * wa0 * wa1 * G[7] + 2.0 * wa0 * wa2 * G[8] +
                wa1 * wa1 * G[9] + 2.0 * wa1 * wa2 * G[10] + wa2 * wa2 * G[11];
    double xd = wa0 * (wb0 * G[12] + wb1 * G[13] + wb2 * G[14]) +
                wa1 * (wb0 * G[15] + wb1 * G[16] + wb2 * G[17]) +
                wa2 * (wb0 * G[18] + wb1 * G[19] + wb2 * G[20]);
    double dd = wb0 * wb0 * G[21] + 2.0 * wb0 * wb1 * G[22] + 2.0 * wb0 * wb2 * G[23] +
                wb1 * wb1 * G[24] + 2.0 * wb1 * wb2 * G[25] + wb2 * wb2 * G[26];

    double Ey2 = (xx + 2.0 * xd + dd) / NK;
    double var = Ey2 - mean * mean;
    g_mean[t] = (float)mean;
    g_rstd[t] = (float)(1.0 / sqrt(var + EPS));
}

// ---------------------------------------------------------------------------
// Kernel 3: conv + max over k (monotone: normalize+leaky applied after max).
// ---------------------------------------------------------------------------
__global__ void k_out(const float* __restrict__ x, const float* __restrict__ W,
                      float* __restrict__ out) {
    const int b = blockIdx.y;
    const int n = blockIdx.x * blockDim.x + threadIdx.x;

    __shared__ float sW[OCH * 6];
    __shared__ float sM[OCH];
    __shared__ float sR[OCH];
    for (int t = threadIdx.x; t < OCH * 6; t += blockDim.x) sW[t] = W[t];
    if (threadIdx.x < OCH) {
        sM[threadIdx.x] = g_mean[b * OCH + threadIdx.x];
        sR[threadIdx.x] = g_rstd[b * OCH + threadIdx.x];
    }
    __syncthreads();

    const float* xb = x + b * 3 * NPTS;
    const float xi0 = xb[n], xi1 = xb[NPTS + n], xi2 = xb[2 * NPTS + n];
    const int* ip = g_idx + (b * NPTS + n) * KNN;

    float d0[KNN], d1[KNN], d2[KNN];
#pragma unroll
    for (int k = 0; k < KNN; k++) {
        int j = ip[k];
        d0[k] = xb[j] - xi0;
        d1[k] = xb[NPTS + j] - xi1;
        d2[k] = xb[2 * NPTS + j] - xi2;
    }

    float* ob = out + (size_t)b * OCH * NPTS + n;
    for (int o = 0; o < OCH; o++) {
        float wa0 = sW[o * 6 + 0], wa1 = sW[o * 6 + 1], wa2 = sW[o * 6 + 2];
        float wb0 = sW[o * 6 + 3], wb1 = sW[o * 6 + 4], wb2 = sW[o * 6 + 5];
        float p = wa0 * xi0;
        p = fmaf(wa1, xi1, p);
        p = fmaf(wa2, xi2, p);
        float m = -3.4e38f;
#pragma unroll
        for (int k = 0; k < KNN; k++) {
            float y = fmaf(wb2, d2[k], fmaf(wb1, d1[k], fmaf(wb0, d0[k], p)));
            m = fmaxf(m, y);
        }
        float z = (m - sM[o]) * sR[o];
        ob[(size_t)o * NPTS] = (z >= 0.f) ? z : SLOPE * z;
    }
}

// ---------------------------------------------------------------------------
extern "C" void kernel_launch(void* const* d_in, const int* in_sizes, int n_in,
                              void* d_out, int out_size) {
    const float* x = (const float*)d_in[0];   // [B, C, N]
    const float* W = (const float*)d_in[1];   // [O, 2C]
    float* out = (float*)d_out;               // [B, O, N]

    cudaFuncSetAttribute(k_knn, cudaFuncAttributeMaxDynamicSharedMemorySize,
                         SMEM_TOTAL);

    dim3 grid(NPTS / 256, B);

    k_init<<<1, 128>>>();
    k_knn<<<grid, 256, SMEM_TOTAL>>>(x);
    k_norm<<<1, B * OCH>>>(W);
    k_out<<<grid, 256>>>(x, W, out);
}

// round 7
// speedup vs baseline: 3.0859x; 1.4186x over previous
#include <cuda_runtime.h>
#include <math.h>
#include <stdint.h>

// Problem constants
#define B 4
#define NPTS 8192
#define KNN 20
#define OCH 64
#define EPS 1e-5
#define SLOPE 0.2f
#define INFF __int_as_float(0x7f800000)

// dynamic smem layout: [0,128K) staged points, [128K,192K) per-lane queues
#define PTS_BYTES (NPTS * 16)
#define BUF_BYTES (8 * 32 * 32 * 8)     // 8 warps x 32 entries x 32 lanes x 8B
#define SMEM_TOTAL (PTS_BYTES + BUF_BYTES)

// Device scratch (no allocations allowed)
__device__ int    g_idx[B * NPTS * KNN];
__device__ double g_stats[B * 27];
__device__ float  g_mean[B * OCH];
__device__ float  g_rstd[B * OCH];

// ---------------------------------------------------------------------------
// Kernel 0: zero the moment accumulators (must happen every call)
// ---------------------------------------------------------------------------
__global__ void k_init() {
    int t = threadIdx.x;
    if (t < B * 27) g_stats[t] = 0.0;
}

// ---------------------------------------------------------------------------
// Branchless stable insertion into sorted-ascending (d, j) list of 20.
// Upper-bound placement (strict <): incoming value lands AFTER existing
// equal-d entries. Since candidates arrive in ascending j, ties are ordered
// by ascending j automatically, and the evicted worst is the largest (d, j)
// lexicographically == jax top_k boundary semantics. Idempotent for vd=+INF.
// ---------------------------------------------------------------------------
__device__ __forceinline__ void insert_dj(float (&sd)[KNN], int (&sj)[KNN],
                                          float vd, int vj) {
    bool c[KNN];
#pragma unroll
    for (int k = 0; k < KNN; k++) c[k] = vd < sd[k];
#pragma unroll
    for (int k = KNN - 1; k >= 1; k--) {
        float td = c[k] ? vd : sd[k];
        int   tj = c[k] ? vj : sj[k];
        sd[k] = c[k - 1] ? sd[k - 1] : td;
        sj[k] = c[k - 1] ? sj[k - 1] : tj;
    }
    sd[0] = c[0] ? vd : sd[0];
    sj[0] = c[0] ? vj : sj[0];
}

// ---------------------------------------------------------------------------
// Kernel 1: single-phase exact KNN + fused moment accumulation.
// Hot loop: per 16-point group, PHASE 1 computes all 16 distances with no
// inline asm in scope (LDS.128 loads batch & pipeline freely), PHASE 2 does
// the 16 predicated queue stores (PTX @p store, no BSSY; the asm memory
// clobbers only order the cheap stores against each other). One uniform
// drain-check branch per group.
// ---------------------------------------------------------------------------
__global__ void k_knn(const float* __restrict__ x) {
    extern __shared__ char sm[];
    float4* s_pts = (float4*)sm;
    __shared__ double sh[27];

    const int b = blockIdx.y;
    const float* xb = x + b * 3 * NPTS;

    // stage points scaled {-2x,-2y,-2z, ||x||^2}
    for (int j = threadIdx.x; j < NPTS; j += blockDim.x) {
        float a0 = xb[j];
        float a1 = xb[NPTS + j];
        float a2 = xb[2 * NPTS + j];
        float sq = fmaf(a0, a0, fmaf(a1, a1, a2 * a2));
        s_pts[j] = make_float4(-2.0f * a0, -2.0f * a1, -2.0f * a2, sq);
    }
    __syncthreads();

    const int tid = threadIdx.x;
    const int i = blockIdx.x * blockDim.x + tid;
    const float4 ps = s_pts[i];
    const float qx = -0.5f * ps.x, qy = -0.5f * ps.y, qz = -0.5f * ps.z;
    const float qw = ps.w;

    // lane-private queue: entry e at byte offset e*256 from bufA
    uint32_t sbase;
    asm("{ .reg .u64 t; cvta.to.shared.u64 t, %1; cvt.u32.u64 %0, t; }"
        : "=r"(sbase) : "l"(sm));
    const uint32_t bufA = sbase + (uint32_t)PTS_BYTES +
                          (uint32_t)(tid >> 5) * 8192u + (uint32_t)(tid & 31) * 8u;
    const float2* bufP = (const float2*)(sm + PTS_BYTES +
                          (tid >> 5) * 8192 + (tid & 31) * 8);

    float sd[KNN];
    int   sj[KNN];
#pragma unroll
    for (int k = 0; k < KNN; k++) { sd[k] = INFF; sj[k] = 0; }
    float worst = INFF;   // stays INF until list holds 20 real entries
    int   cnt = 0;

#define DRAIN() do {                                                   \
        for (int e = 0; __any_sync(0xffffffffu, e < cnt); e++) {       \
            float2 v = bufP[e * 32];                                   \
            float vd = (e < cnt) ? v.x : INFF;                         \
            insert_dj(sd, sj, vd, __float_as_int(v.y));                \
        }                                                              \
        worst = sd[KNN - 1];                                           \
        cnt = 0;                                                       \
    } while (0)

    for (int j0 = 0; j0 < NPTS; j0 += 16) {
        // PHASE 1: pure loads + math (no asm in scope -> batched LDS.128)
        float dv[16];
#pragma unroll
        for (int u = 0; u < 16; u++) {
            float4 p = s_pts[j0 + u];
            dv[u] = fmaf(qz, p.z, fmaf(qy, p.y, fmaf(qx, p.x, qw + p.w)));
        }
        // PHASE 2: predicated queue stores (branch-free)
#pragma unroll
        for (int u = 0; u < 16; u++) {
            bool t = dv[u] < worst;               // strict <: exact (see proof)
            uint32_t a = bufA + (uint32_t)cnt * 256u;
            asm volatile(
                "{ .reg .pred p; setp.ne.u32 p, %0, 0;"
                "  @p st.shared.v2.b32 [%1], {%2, %3}; }"
                :: "r"((uint32_t)t), "r"(a), "r"(__float_as_int(dv[u])),
                   "r"(j0 + u)
                : "memory");
            cnt += t;
        }
        // cap proof: post-check cnt <= 15, +16 -> <= 31 < 32 slots
        if (__any_sync(0xffffffffu, cnt >= 16)) DRAIN();
    }
    DRAIN();   // leftovers
#undef DRAIN

    int* op = g_idx + (b * NPTS + i) * KNN;
#pragma unroll
    for (int k = 0; k < KNN; k++) op[k] = sj[k];

    // ---------------- fused moment accumulation ----------------
    // deltas: xj - xi = (-0.5*p.x) - qx  (exact power-of-two rescale)
    const float nqx = -qx, nqy = -qy, nqz = -qz;
    float sd0 = 0.f, sd1 = 0.f, sd2 = 0.f;
    float s00 = 0.f, s01 = 0.f, s02 = 0.f, s11 = 0.f, s12 = 0.f, s22 = 0.f;
#pragma unroll
    for (int k = 0; k < KNN; k++) {
        float4 p = s_pts[sj[k]];
        float d0 = fmaf(-0.5f, p.x, nqx);
        float d1 = fmaf(-0.5f, p.y, nqy);
        float d2 = fmaf(-0.5f, p.z, nqz);
        sd0 += d0; sd1 += d1; sd2 += d2;
        s00 = fmaf(d0, d0, s00); s01 = fmaf(d0, d1, s01); s02 = fmaf(d0, d2, s02);
        s11 = fmaf(d1, d1, s11); s12 = fmaf(d1, d2, s12); s22 = fmaf(d2, d2, s22);
    }

    float v[27];
    v[0] = KNN * qx; v[1] = KNN * qy; v[2] = KNN * qz;
    v[3] = sd0; v[4] = sd1; v[5] = sd2;
    v[6] = KNN * qx * qx; v[7] = KNN * qx * qy; v[8]  = KNN * qx * qz;
    v[9] = KNN * qy * qy; v[10] = KNN * qy * qz; v[11] = KNN * qz * qz;
    v[12] = qx * sd0; v[13] = qx * sd1; v[14] = qx * sd2;
    v[15] = qy * sd0; v[16] = qy * sd1; v[17] = qy * sd2;
    v[18] = qz * sd0; v[19] = qz * sd1; v[20] = qz * sd2;
    v[21] = s00; v[22] = s01; v[23] = s02; v[24] = s11; v[25] = s12; v[26] = s22;

#pragma unroll
    for (int q = 0; q < 27; q++) {
#pragma unroll
        for (int off = 16; off > 0; off >>= 1)
            v[q] += __shfl_down_sync(0xffffffffu, v[q], off);
    }

    if (threadIdx.x < 27) sh[threadIdx.x] = 0.0;
    __syncthreads();
    if ((threadIdx.x & 31) == 0) {
#pragma unroll
        for (int q = 0; q < 27; q++) atomicAdd(&sh[q], (double)v[q]);
    }
    __syncthreads();
    if (threadIdx.x < 27) atomicAdd(&g_stats[b * 27 + threadIdx.x], sh[threadIdx.x]);
}

// ---------------------------------------------------------------------------
// Kernel 2: per-(b,o) mean / rstd from the quadratic form.  256 threads.
// ---------------------------------------------------------------------------
__global__ void k_norm(const float* __restrict__ W) {
    int t = threadIdx.x;
    int b = t / OCH, o = t % OCH;
    const float* w = W + o * 6;
    double wa0 = w[0], wa1 = w[1], wa2 = w[2];
    double wb0 = w[3], wb1 = w[4], wb2 = w[5];
    const double* G = g_stats + b * 27;
    const double NK = (double)NPTS * (double)KNN;

    double mean = (wa0 * G[0] + wa1 * G[1] + wa2 * G[2] +
                   wb0 * G[3] + wb1 * G[4] + wb2 * G[5]) / NK;

    double xx = wa0 * wa0 * G[6] + 2.0 * wa0 * wa1 * G[7] + 2.0 * wa0 * wa2 * G[8] +
                wa1 * wa1 * G[9] + 2.0 * wa1 * wa2 * G[10] + wa2 * wa2 * G[11];
    double xd = wa0 * (wb0 * G[12] + wb1 * G[13] + wb2 * G[14]) +
                wa1 * (wb0 * G[15] + wb1 * G[16] + wb2 * G[17]) +
                wa2 * (wb0 * G[18] + wb1 * G[19] + wb2 * G[20]);
    double dd = wb0 * wb0 * G[21] + 2.0 * wb0 * wb1 * G[22] + 2.0 * wb0 * wb2 * G[23] +
                wb1 * wb1 * G[24] + 2.0 * wb1 * wb2 * G[25] + wb2 * wb2 * G[26];

    double Ey2 = (xx + 2.0 * xd + dd) / NK;
    double var = Ey2 - mean * mean;
    g_mean[t] = (float)mean;
    g_rstd[t] = (float)(1.0 / sqrt(var + EPS));
}

// ---------------------------------------------------------------------------
// Kernel 3: conv + max over k (monotone: normalize+leaky applied after max).
// ---------------------------------------------------------------------------
__global__ void k_out(const float* __restrict__ x, const float* __restrict__ W,
                      float* __restrict__ out) {
    const int b = blockIdx.y;
    const int n = blockIdx.x * blockDim.x + threadIdx.x;

    __shared__ float sW[OCH * 6];
    __shared__ float sM[OCH];
    __shared__ float sR[OCH];
    for (int t = threadIdx.x; t < OCH * 6; t += blockDim.x) sW[t] = W[t];
    if (threadIdx.x < OCH) {
        sM[threadIdx.x] = g_mean[b * OCH + threadIdx.x];
        sR[threadIdx.x] = g_rstd[b * OCH + threadIdx.x];
    }
    __syncthreads();

    const float* xb = x + b * 3 * NPTS;
    const float xi0 = xb[n], xi1 = xb[NPTS + n], xi2 = xb[2 * NPTS + n];
    const int* ip = g_idx + (b * NPTS + n) * KNN;

    float d0[KNN], d1[KNN], d2[KNN];
#pragma unroll
    for (int k = 0; k < KNN; k++) {
        int j = ip[k];
        d0[k] = xb[j] - xi0;
        d1[k] = xb[NPTS + j] - xi1;
        d2[k] = xb[2 * NPTS + j] - xi2;
    }

    float* ob = out + (size_t)b * OCH * NPTS + n;
    for (int o = 0; o < OCH; o++) {
        float wa0 = sW[o * 6 + 0], wa1 = sW[o * 6 + 1], wa2 = sW[o * 6 + 2];
        float wb0 = sW[o * 6 + 3], wb1 = sW[o * 6 + 4], wb2 = sW[o * 6 + 5];
        float p = wa0 * xi0;
        p = fmaf(wa1, xi1, p);
        p = fmaf(wa2, xi2, p);
        float m = -3.4e38f;
#pragma unroll
        for (int k = 0; k < KNN; k++) {
            float y = fmaf(wb2, d2[k], fmaf(wb1, d1[k], fmaf(wb0, d0[k], p)));
            m = fmaxf(m, y);
        }
        float z = (m - sM[o]) * sR[o];
        ob[(size_t)o * NPTS] = (z >= 0.f) ? z : SLOPE * z;
    }
}

// ---------------------------------------------------------------------------
extern "C" void kernel_launch(void* const* d_in, const int* in_sizes, int n_in,
                              void* d_out, int out_size) {
    const float* x = (const float*)d_in[0];   // [B, C, N]
    const float* W = (const float*)d_in[1];   // [O, 2C]
    float* out = (float*)d_out;               // [B, O, N]

    cudaFuncSetAttribute(k_knn, cudaFuncAttributeMaxDynamicSharedMemorySize,
                         SMEM_TOTAL);

    dim3 grid(NPTS / 256, B);

    k_init<<<1, 128>>>();
    k_knn<<<grid, 256, SMEM_TOTAL>>>(x);
    k_norm<<<1, B * OCH>>>(W);
    k_out<<<grid, 256>>>(x, W, out);
}